// round 14
// baseline (speedup 1.0000x reference)
#include <cuda_runtime.h>
#include <cstdint>

// Problem constants (upper bounds; runtime shapes read from in_sizes)
#define NMAX 16384
#define PMAX 4096
#define NB   16384              // rank buckets
#define RMAX (NMAX + PMAX)      // 20480 distinct ranks max

#define G_BLOCKS 128
#define B_THREADS 512

typedef unsigned int u32;
typedef unsigned short u16;

// -------- cross-kernel scratch (allocation-free: __device__ globals) --------
__device__ u16 g_writer[PMAX];        // last writer item per slot, 0xFFFF = keep original
__device__ u32 g_hist[RMAX];          // pool-rank histogram
__device__ u32 g_cursor[RMAX];        // psBelow -> U cursors
__device__ u32 g_bdata[RMAX];         // okeys by bucket (front) / accepted list (resolve)
__device__ u16 g_rank_scores[NMAX];   // exact rank of each score
__device__ u16 g_rank_prior[PMAX];    // exact rank of each input priority
__device__ u16 g_sr[NMAX];            // stream ranks
__device__ u16 g_si[NMAX];            // stream item ids
__device__ u16 g_chunkS[NMAX];        // per-256-chunk sorted stream ranks
__device__ u16 g_psr[PMAX];           // poolstart ranks
__device__ u32 g_Bq[NMAX];            // dominance counts
__device__ int g_T, g_fc, g_room, g_C0;

// front-end pipeline scratch
__device__ u32 g_bhist[NB];           // bucket histogram
__device__ u32 g_bprefix[NB];         // bucket start
__device__ u32 g_bcur[NB];            // bucket cursor/end
__device__ u32 g_bpart[G_BLOCKS];     // scan partials (buckets)
__device__ u32 g_cpart[G_BLOCKS];     // classify partials
__device__ u32 g_coff[G_BLOCKS];      // classify block offsets
__device__ u32 g_ppart[G_BLOCKS];     // psBelow partials
__device__ u32 g_poff[G_BLOCKS];      // psBelow block offsets

// software grid barrier state (persists across launches; gen is monotonic)
__device__ unsigned int g_barcnt;
__device__ volatile unsigned int g_bargen;

__device__ __forceinline__ void gridbar() {
    __threadfence();
    __syncthreads();
    if (threadIdx.x == 0) {
        unsigned int gen = g_bargen;
        if (atomicAdd(&g_barcnt, 1u) == (unsigned)(G_BLOCKS - 1)) {
            g_barcnt = 0u;
            __threadfence();
            g_bargen = gen + 1u;
        } else {
            while (g_bargen == gen) { __nanosleep(64); }
        }
    }
    __syncthreads();
}

// cross-block coherent loads (bypass non-coherent L1)
__device__ __forceinline__ u32 LDCG32(const u32* p) { return __ldcg(p); }
__device__ __forceinline__ int  LDCGI(const int* p)  { return __ldcg(p); }
__device__ __forceinline__ u16  LDCG16(const u16* p) {
    unsigned short v;
    asm volatile("ld.global.cg.u16 %0, [%1];" : "=h"(v) : "l"(p));
    return v;
}

// order-preserving u32 transform of float (total order matching IEEE <)
__device__ __forceinline__ u32 okey(float v) {
    u32 b = __float_as_uint(v);
    return (b & 0x80000000u) ? ~b : (b | 0x80000000u);
}
// monotone bucketing (exactness NOT required; monotone + equal-on-equal is)
__device__ __forceinline__ int bucketOf(float v) {
    if (!(v > 0.0f)) return 0;
    if (v >= 1.0f)   return NB - 1;
    int b = (int)(v * 16384.0f);
    return b < 0 ? 0 : (b > NB - 1 ? NB - 1 : b);
}

// inclusive block scan over values held by threads tid < NACT (NACT multiple
// of 32). ALL threads must call (contains __syncthreads). wtot gets warp tails.
template<int NACT>
__device__ __forceinline__ u32 blockScanIncl(u32 h, int tid, int lane, int w, u32* wtot) {
    u32 v = h;
    #pragma unroll
    for (int o = 1; o < 32; o <<= 1) {
        u32 x = __shfl_up_sync(0xFFFFFFFFu, v, o);
        if (lane >= o) v += x;
    }
    if (tid < NACT && lane == 31) wtot[w] = v;
    __syncthreads();
    u32 off = 0;
    if (tid < NACT) {
        #pragma unroll
        for (int j = 0; j < NACT / 32; ++j) if (j < w) off += wtot[j];
    }
    return v + off;
}

// ---------------------------------------------------------------------------
// k_all: the ENTIRE pipeline in one persistent grid (128 blocks x 512).
// Phases separated by software grid barriers. Front end + count are
// full-chip; resolve runs on block 0 (single-block phase); copy is
// grid-strided. Logic is a 1:1 port of the verified R12 kernels.
// ---------------------------------------------------------------------------
__global__ __launch_bounds__(B_THREADS, 1)
void k_all(const float* __restrict__ scores,
           const float* __restrict__ priorities,
           const int* __restrict__ countp,
           const float* __restrict__ pool,
           const float* __restrict__ summaries,
           float* __restrict__ out,
           int N, int P, int D, long long out_size) {
    extern __shared__ u32 S[];             // resolve scratch (block 0 only)
    __shared__ u32 wtot[16];
    __shared__ u32 wcnt[16];
    __shared__ u16 chunkbuf[256];
    __shared__ int wsum[32];
    __shared__ int sh_changed, sh_anyTies, sh_A;

    const int tid  = threadIdx.x;
    const int b    = blockIdx.x;
    const int gtid = b * B_THREADS + tid;
    const int lane = tid & 31, w = tid >> 5;
    const int M = N + P;

    // ==================== FRONT END (verified R12 logic) ====================
    // ---- ph0: zero scratch ----
    if (gtid < NB)   g_bhist[gtid]  = 0u;
    if (gtid < RMAX) g_hist[gtid]   = 0u;
    if (gtid < PMAX) g_writer[gtid] = 0xFFFFu;
    gridbar();

    // ---- ph1: bucket histogram ----
    if (gtid < M) {
        float v = (gtid < N) ? scores[gtid] : priorities[gtid - N];
        atomicAdd(&g_bhist[bucketOf(v)], 1u);
    }
    gridbar();

    // ---- ph2a: block-local scan of this block's 128-bucket segment ----
    u32 h2 = 0, incl2 = 0;
    {
        if (tid < 128) h2 = LDCG32(&g_bhist[b * 128 + tid]);
        incl2 = blockScanIncl<128>(h2, tid, lane, w, wtot);
        if (tid == 0) g_bpart[b] = wtot[0] + wtot[1] + wtot[2] + wtot[3];
    }
    gridbar();

    // ---- ph2b: block0 exclusive-scans g_bpart in place ----
    if (b == 0) {
        u32 hB = (tid < 128) ? LDCG32(&g_bpart[tid]) : 0u;
        u32 inclB = blockScanIncl<128>(hB, tid, lane, w, wtot);
        __syncthreads();
        if (tid < 128) g_bpart[tid] = inclB - hB;
    }
    gridbar();

    // ---- ph2c: final bucket prefixes + cursors ----
    if (tid < 128) {
        u32 off = LDCG32(&g_bpart[b]);
        u32 pre = off + (incl2 - h2);
        int idx = b * 128 + tid;
        g_bprefix[idx] = pre;
        g_bcur[idx]    = pre;
    }
    gridbar();

    // ---- ph3: scatter okeys by bucket ----
    if (gtid < M) {
        float v = (gtid < N) ? scores[gtid] : priorities[gtid - N];
        u32 pos = atomicAdd(&g_bcur[bucketOf(v)], 1u);
        g_bdata[pos] = okey(v);
    }
    gridbar();

    // ---- ph4: exact ranks + classify partials ----
    if (gtid < M) {
        float v = (gtid < N) ? scores[gtid] : priorities[gtid - N];
        u16 r;
        if (!(v > 0.0f)) {
            r = 0;
        } else {
            int bb = bucketOf(v);
            u32 k = okey(v);
            u32 s0 = LDCG32(&g_bprefix[bb]), e0 = LDCG32(&g_bcur[bb]);
            u32 c = 0;
            for (u32 j = s0; j < e0; ++j) c += (LDCG32(&g_bdata[j]) < k) ? 1u : 0u;
            r = (u16)(s0 + c);
        }
        if (gtid < N) g_rank_scores[gtid] = r; else g_rank_prior[gtid - N] = r;
    }
    const bool f = (gtid < N) && (scores[gtid] > 0.5f);
    u32 fmask = __ballot_sync(0xFFFFFFFFu, f);
    const u32 lanepref = __popc(fmask & ((1u << lane) - 1u));
    if (lane == 0) wcnt[w] = __popc(fmask);
    __syncthreads();
    if (tid == 0) {
        u32 tot = 0;
        #pragma unroll
        for (int j = 0; j < 16; ++j) tot += wcnt[j];
        g_cpart[b] = tot;
    }
    gridbar();

    // ---- ph5: block0 scans g_cpart -> g_coff; metas ----
    if (b == 0) {
        u32 hC = (tid < 128) ? LDCG32(&g_cpart[tid]) : 0u;
        u32 inclC = blockScanIncl<128>(hC, tid, lane, w, wtot);
        if (tid < 128) g_coff[tid] = inclC - hC;
        if (tid == 0) {
            int total = (int)(wtot[0] + wtot[1] + wtot[2] + wtot[3]);
            int C0 = *countp;
            int room = P - C0; if (room < 0) room = 0;
            g_T    = (total > room) ? total - room : 0;
            g_fc   = C0 + ((total < room) ? total : room);
            g_room = room;
            g_C0   = C0;
        }
    }
    gridbar();

    // ---- ph6: classify writes (appends + phase-2 stream) ----
    if (f) {
        int room = LDCGI(&g_room);
        int C0   = LDCGI(&g_C0);
        u32 woff = 0;
        #pragma unroll
        for (int j = 0; j < 16; ++j) if (j < w) woff += wcnt[j];
        int r = (int)(LDCG32(&g_coff[b]) + woff + lanepref);
        if (r < room) g_writer[C0 + r] = (u16)gtid;
        else          g_si[r - room]   = (u16)gtid;
    }
    gridbar();

    // ---- ph7: pool ranks + hist, stream ranks ----
    {
        int T = LDCGI(&g_T);
        if (gtid < P) {
            u16 wv = LDCG16(&g_writer[gtid]);
            u16 pr = (wv != 0xFFFFu) ? LDCG16(&g_rank_scores[wv])
                                     : LDCG16(&g_rank_prior[gtid]);
            g_psr[gtid] = pr;
            atomicAdd(&g_hist[pr], 1u);
        }
        if (gtid < T) {
            u16 it = LDCG16(&g_si[gtid]);
            g_sr[gtid] = LDCG16(&g_rank_scores[it]);
        }
    }
    gridbar();

    // ---- ph8a: psBelow partials (160/block) + chunk sorts (blocks 0..63) ----
    u32 h8 = 0, incl8 = 0;
    {
        if (tid < 160) h8 = LDCG32(&g_hist[b * 160 + tid]);
        incl8 = blockScanIncl<160>(h8, tid, lane, w, wtot);
        if (tid == 0) g_ppart[b] = wtot[0] + wtot[1] + wtot[2] + wtot[3] + wtot[4];
        __syncthreads();
    }
    if (b < 64) {
        int T = LDCGI(&g_T);
        if (tid < 256) {
            int i = (b << 8) + tid;
            chunkbuf[tid] = (i < T) ? LDCG16(&g_sr[i]) : (u16)0xFFFFu;
        }
        __syncthreads();
        for (int k = 2; k <= 256; k <<= 1) {
            for (int j = k >> 1; j > 0; j >>= 1) {
                if (tid < 256) {
                    int p = tid ^ j;
                    if (p > tid) {
                        u16 x = chunkbuf[tid], y = chunkbuf[p];
                        bool up = ((tid & k) == 0);
                        if (up ? (x > y) : (x < y)) { chunkbuf[tid] = y; chunkbuf[p] = x; }
                    }
                }
                __syncthreads();
            }
        }
        if (tid < 256) g_chunkS[(b << 8) + tid] = chunkbuf[tid];
    }
    gridbar();

    // ---- ph8b: block0 scans g_ppart -> g_poff ----
    if (b == 0) {
        u32 hP = (tid < 128) ? LDCG32(&g_ppart[tid]) : 0u;
        u32 inclP = blockScanIncl<128>(hP, tid, lane, w, wtot);
        if (tid < 128) g_poff[tid] = inclP - hP;
    }
    gridbar();

    // ---- ph8c: psBelow -> g_cursor ----
    if (tid < 160) {
        u32 off = LDCG32(&g_poff[b]);
        g_cursor[b * 160 + tid] = off + (incl8 - h8);
    }
    gridbar();

    // ==================== COUNT (grid-wide, one warp per item) =============
    // g_sr / g_chunkS are written in block-aligned contiguous ranges, so a
    // block's L1 can only hold lines it wrote itself -> plain loads are safe
    // and keep the hot binary searches L1-cached.
    {
        const int T = LDCGI(&g_T);
        const int warpsTotal = (G_BLOCKS * B_THREADS) >> 5;
        const int gw = gtid >> 5;
        for (int q = gw; q < T; q += warpsTotal) {
            const u16 r = g_sr[q];
            const int c0 = q >> 8;
            u32 cnt = 0;
            for (int ch = lane; ch < c0; ch += 32) {
                const u16* a = g_chunkS + (ch << 8);
                int lo = 0, hi = 256;
                while (lo < hi) { int m = (lo + hi) >> 1; if (a[m] < r) lo = m + 1; else hi = m; }
                cnt += (u32)lo;
            }
            for (int j = (q & ~255) + lane; j < q; j += 32)
                cnt += (g_sr[j] < r) ? 1u : 0u;
            #pragma unroll
            for (int o = 16; o; o >>= 1) cnt += __shfl_down_sync(0xFFFFFFFFu, cnt, o);
            if (lane == 0) g_Bq[q] = cnt;
        }
    }
    gridbar();

    // ==================== RESOLVE (block 0; verified R12 logic, 512 thr) ===
    if (b == 0) {
        u32* gU  = S;                          // RMAX
        u32* par = S + RMAX;                   // NMAX
        u16* wr  = (u16*)(S + RMAX + NMAX);    // PMAX
        const int nthr = B_THREADS;
        const int T = LDCGI(&g_T);

        // ---- accept: 32 items/thread ----
        {
            int myCnt = 0;
            u32 amask = 0;
            const int q0 = tid * 32;
            u16 rs[32];
            #pragma unroll
            for (int j = 0; j < 32; ++j) {
                int q = q0 + j;
                if (q < T) {
                    u16 r = LDCG16(&g_sr[q]);
                    rs[j] = r;
                    int bq = (int)LDCG32(&g_Bq[q]);
                    int psb = (int)LDCG32(&g_cursor[r]);
                    if (psb + bq >= q + 1) { amask |= (1u << j); myCnt++; }
                }
            }
            int vv = myCnt;
            #pragma unroll
            for (int o = 1; o < 32; o <<= 1) {
                int t = __shfl_up_sync(0xFFFFFFFFu, vv, o);
                if (lane >= o) vv += t;
            }
            if (lane == 31) wsum[w] = vv;
            __syncthreads();
            if (w == 0) {
                int ww = (lane < 16) ? wsum[lane] : 0;
                #pragma unroll
                for (int o = 1; o < 32; o <<= 1) {
                    int t = __shfl_up_sync(0xFFFFFFFFu, ww, o);
                    if (lane >= o) ww += t;
                }
                if (lane < 16) wsum[lane] = ww;
            }
            __syncthreads();
            int jbase = (vv - myCnt) + ((w > 0) ? wsum[w - 1] : 0);
            if (tid == 0) sh_A = wsum[15];
            #pragma unroll
            for (int j = 0; j < 32; ++j) {
                if (amask & (1u << j)) {
                    int q = q0 + j;
                    g_bdata[jbase++] = ((u32)rs[j] << 14) | (u32)LDCG16(&g_si[q]);
                }
            }
            __syncthreads();
        }
        const int A = sh_A;

        for (int i = tid; i < PMAX; i += nthr)
            wr[i] = (i < P) ? LDCG16(&g_writer[i]) : (u16)0xFFFFu;
        __syncthreads();

        if (A > 0) {
            const int UN = P + A;

            for (int j = tid; j < A; j += nthr) atomicAdd(&g_hist[g_bdata[j] >> 14], 1u);
            __syncthreads();
            {   // exclusive prefix over RMAX -> g_cursor (U cursors)
                const int CPT = RMAX / B_THREADS;   // 40
                const int base = tid * CPT;
                u32 s = 0;
                #pragma unroll
                for (int j = 0; j < CPT; ++j) s += LDCG32(&g_hist[base + j]);
                u32 vv = s;
                #pragma unroll
                for (int o = 1; o < 32; o <<= 1) {
                    u32 t = __shfl_up_sync(0xFFFFFFFFu, vv, o);
                    if (lane >= o) vv += t;
                }
                if (lane == 31) wsum[w] = (int)vv;
                __syncthreads();
                if (w == 0) {
                    u32 ww = (lane < 16) ? (u32)wsum[lane] : 0u;
                    #pragma unroll
                    for (int o = 1; o < 32; o <<= 1) {
                        u32 t = __shfl_up_sync(0xFFFFFFFFu, ww, o);
                        if (lane >= o) ww += t;
                    }
                    if (lane < 16) wsum[lane] = (int)ww;
                }
                __syncthreads();
                u32 run = (vv - s) + ((w > 0) ? (u32)wsum[w - 1] : 0u);
                #pragma unroll
                for (int j = 0; j < CPT; ++j) {
                    u32 h = LDCG32(&g_hist[base + j]);
                    g_cursor[base + j] = run;
                    run += h;
                }
                __syncthreads();
            }
            // scatter: elem = rank<<17 | type<<16 | id
            for (int i = tid; i < P; i += nthr) {
                u32 r = (u32)LDCG16(&g_psr[i]);
                u32 pos = atomicAdd(&g_cursor[r], 1u);
                gU[pos] = (r << 17) | (u32)i;
            }
            for (int j = tid; j < A; j += nthr) {
                u32 r = g_bdata[j] >> 14;
                u32 pos = atomicAdd(&g_cursor[r], 1u);
                gU[pos] = (r << 17) | 0x10000u | (u32)j;
            }
            __syncthreads();

            if (tid == 0) sh_anyTies = 0;
            __syncthreads();
            for (int p = tid; p + 1 < UN; p += nthr)
                if ((gU[p] >> 17) == (gU[p + 1] >> 17)) sh_anyTies = 1;
            __syncthreads();

            const int MAXIT = 32;
            for (int it = 0; it < MAXIT; ++it) {
                for (int j = tid; j < A; j += nthr) {
                    u32 e = gU[j];
                    par[j] = (e & 0x10000u) ? (e & 0xFFFFu) : (0x80000000u | (e & 0xFFFFu));
                }
                __syncthreads();
                for (int rd = 0; rd < 15; ++rd) {
                    if (tid == 0) sh_changed = 0;
                    __syncthreads();
                    for (int j = tid; j < A; j += nthr) {
                        u32 pv = par[j];
                        if (!(pv & 0x80000000u)) {
                            u32 g = par[pv];
                            par[j] = g;
                            if (!(g & 0x80000000u)) sh_changed = 1;
                        }
                    }
                    __syncthreads();
                    if (!sh_changed) break;
                }
                if (!sh_anyTies) break;
                if (it == MAXIT - 1) break;
                if (tid == 0) sh_changed = 0;
                __syncthreads();
                for (int p = tid; p < UN; p += nthr) {
                    u32 r = gU[p] >> 17;
                    bool leader = (p == 0) || ((gU[p - 1] >> 17) != r);
                    if (leader && p + 1 < UN && (gU[p + 1] >> 17) == r) {
                        int len = 1;
                        while (p + len < UN && (gU[p + len] >> 17) == r) len++;
                        bool ch = false;
                        for (int a = 1; a < len; ++a) {
                            u32 x = gU[p + a];
                            u32 sx = (x & 0x10000u) ? (par[x & 0xFFFFu] & 0xFFFFu) : (x & 0xFFFFu);
                            u32 kx = (sx << 1) | ((x >> 16) & 1u);
                            int bb = a;
                            while (bb > 0) {
                                u32 y = gU[p + bb - 1];
                                u32 sy = (y & 0x10000u) ? (par[y & 0xFFFFu] & 0xFFFFu) : (y & 0xFFFFu);
                                u32 ky = (sy << 1) | ((y >> 16) & 1u);
                                if (ky <= kx) break;
                                gU[p + bb] = y; bb--; ch = true;
                            }
                            gU[p + bb] = x;
                        }
                        if (ch) sh_changed = 1;
                    }
                }
                __syncthreads();
                if (!sh_changed) break;
            }

            for (int pos = A + tid; pos < UN; pos += nthr) {
                u32 e = gU[pos];
                if (e & 0x10000u) {
                    u32 j = e & 0xFFFFu;
                    u32 s = par[j] & 0xFFFFu;
                    if (s < (u32)P) wr[s] = (u16)(g_bdata[j] & 0x3FFFu);
                }
            }
            __syncthreads();
        }

        // epilogue: final writer map + priorities + count
        const long long obase = (long long)P * (long long)D;
        for (int i = tid; i < P; i += nthr) {
            u16 wv = wr[i];
            g_writer[i] = wv;
            if (obase + i < out_size)
                out[obase + i] = (wv != 0xFFFFu) ? scores[wv] : priorities[i];
        }
        if (tid == 0 && obase + P < out_size)
            out[obase + P] = (float)LDCGI(&g_fc);
    }
    gridbar();

    // ==================== COPY (grid-strided rows) =========================
    // g_writer was rewritten by block 0 post-barrier -> .cg loads.
    if ((D & 3) == 0) {
        const int D4 = D >> 2;
        const long long total = (long long)P * (long long)D4;
        const long long stride = (long long)G_BLOCKS * B_THREADS;
        for (long long idx = gtid; idx < total; idx += stride) {
            int row = (int)(idx / D4);
            int col = (int)(idx - (long long)row * D4);
            u16 wv = LDCG16(&g_writer[row]);
            const float4* src = (wv == 0xFFFFu)
                ? (const float4*)(pool + (long long)row * D)
                : (const float4*)(summaries + (long long)wv * D);
            ((float4*)(out + (long long)row * D))[col] = src[col];
        }
    } else {
        const long long total = (long long)P * (long long)D;
        const long long stride = (long long)G_BLOCKS * B_THREADS;
        for (long long idx = gtid; idx < total; idx += stride) {
            int row = (int)(idx / D);
            int col = (int)(idx - (long long)row * D);
            u16 wv = LDCG16(&g_writer[row]);
            const float* src = (wv == 0xFFFFu) ? (pool + (long long)row * D)
                                               : (summaries + (long long)wv * D);
            out[(long long)row * D + col] = src[col];
        }
    }
}

// ---------------------------------------------------------------------------
// Inputs (metadata order): summaries[N,D] f32, scores[N] f32, pool[P,D] f32,
// priorities[P] f32, count i32 scalar.
// Output: concat(pool_out[P*D], priorities[P], count) as f32.
// ---------------------------------------------------------------------------
extern "C" void kernel_launch(void* const* d_in, const int* in_sizes, int n_in,
                              void* d_out, int out_size) {
    const float* summaries  = (const float*)d_in[0];
    const float* scores     = (const float*)d_in[1];
    const float* pool       = (const float*)d_in[2];
    const float* priorities = (const float*)d_in[3];
    const int*   countp     = (const int*)d_in[4];

    const int N = in_sizes[1];
    const int P = in_sizes[3];
    const int D = (N > 0) ? (in_sizes[0] / N) : 0;
    float* out = (float*)d_out;

    const int smem = (RMAX + NMAX) * 4 + PMAX * 2;   // 155,648 (resolve scratch)
    cudaFuncSetAttribute(k_all, cudaFuncAttributeMaxDynamicSharedMemorySize, smem);

    k_all<<<G_BLOCKS, B_THREADS, smem>>>(scores, priorities, countp,
                                         pool, summaries, out,
                                         N, P, D, (long long)out_size);
}

// round 17
// speedup vs baseline: 1.2067x; 1.2067x over previous
#include <cuda_runtime.h>
#include <cstdint>

// Problem constants (upper bounds; runtime shapes read from in_sizes)
#define NMAX 16384
#define PMAX 4096
#define NB   16384              // rank buckets
#define RMAX (NMAX + PMAX)      // 20480 distinct ranks max

#define G_BLOCKS 128
#define B_THREADS 1024

typedef unsigned int u32;
typedef unsigned short u16;

// -------- cross-kernel scratch (allocation-free: __device__ globals) --------
__device__ u16 g_writer[PMAX];        // last writer item per slot, 0xFFFF = keep original
__device__ u32 g_hist[RMAX];          // pool-rank histogram
__device__ u32 g_cursor[RMAX];        // psBelow -> U cursors
__device__ u32 g_bdata[RMAX];         // okeys by bucket (front) / accepted list (resolve)
__device__ u16 g_rank_scores[NMAX];   // exact rank of each score
__device__ u16 g_rank_prior[PMAX];    // exact rank of each input priority
__device__ u16 g_sr[NMAX];            // stream ranks
__device__ u16 g_si[NMAX];            // stream item ids
__device__ u16 g_chunkS[NMAX];        // per-256-chunk sorted stream ranks
__device__ u16 g_psr[PMAX];           // poolstart ranks
__device__ u32 g_Bq[NMAX];            // dominance counts
__device__ int g_T, g_fc, g_room, g_C0;

// front-end pipeline scratch
__device__ u32 g_bhist[NB];           // bucket histogram
__device__ u32 g_bprefix[NB];         // bucket start
__device__ u32 g_bcur[NB];            // bucket cursor/end
__device__ u32 g_bpart[G_BLOCKS];     // scan partials (buckets)
__device__ u32 g_cpart[G_BLOCKS];     // classify partials
__device__ u32 g_coff[G_BLOCKS];      // classify block offsets
__device__ u32 g_ppart[G_BLOCKS];     // psBelow partials
__device__ u32 g_poff[G_BLOCKS];      // psBelow block offsets

// software grid barrier state (persists across launches; gen is monotonic)
__device__ unsigned int g_barcnt;
__device__ volatile unsigned int g_bargen;

__device__ __forceinline__ void gridbar() {
    __threadfence();
    __syncthreads();
    if (threadIdx.x == 0) {
        unsigned int gen = g_bargen;
        if (atomicAdd(&g_barcnt, 1u) == (unsigned)(G_BLOCKS - 1)) {
            g_barcnt = 0u;
            __threadfence();
            g_bargen = gen + 1u;
        } else {
            while (g_bargen == gen) { __nanosleep(64); }
        }
    }
    __syncthreads();
}

// cross-block coherent loads (bypass non-coherent L1)
__device__ __forceinline__ u32 LDCG32(const u32* p) { return __ldcg(p); }
__device__ __forceinline__ int  LDCGI(const int* p)  { return __ldcg(p); }
__device__ __forceinline__ u16  LDCG16(const u16* p) {
    unsigned short v;
    asm volatile("ld.global.cg.u16 %0, [%1];" : "=h"(v) : "l"(p));
    return v;
}

// order-preserving u32 transform of float (total order matching IEEE <)
__device__ __forceinline__ u32 okey(float v) {
    u32 b = __float_as_uint(v);
    return (b & 0x80000000u) ? ~b : (b | 0x80000000u);
}
// monotone bucketing (exactness NOT required; monotone + equal-on-equal is)
__device__ __forceinline__ int bucketOf(float v) {
    if (!(v > 0.0f)) return 0;
    if (v >= 1.0f)   return NB - 1;
    int b = (int)(v * 16384.0f);
    return b < 0 ? 0 : (b > NB - 1 ? NB - 1 : b);
}

// inclusive block scan over values held by threads tid < NACT (NACT multiple
// of 32). ALL threads must call (contains __syncthreads). wtot gets warp tails.
template<int NACT>
__device__ __forceinline__ u32 blockScanIncl(u32 h, int tid, int lane, int w, u32* wtot) {
    u32 v = h;
    #pragma unroll
    for (int o = 1; o < 32; o <<= 1) {
        u32 x = __shfl_up_sync(0xFFFFFFFFu, v, o);
        if (lane >= o) v += x;
    }
    if (tid < NACT && lane == 31) wtot[w] = v;
    __syncthreads();
    u32 off = 0;
    if (tid < NACT) {
        #pragma unroll
        for (int j = 0; j < NACT / 32; ++j) if (j < w) off += wtot[j];
    }
    return v + off;
}

// ---------------------------------------------------------------------------
// k_all: ENTIRE pipeline, one persistent grid (128 blocks x 1024 threads).
// Phase parallelism matches the verified R12 kernels exactly:
//   front end full-chip, count = 4096 warps, resolve = block 0 @1024 threads,
//   copy = 4096 warps grid-strided.
// ---------------------------------------------------------------------------
__global__ __launch_bounds__(B_THREADS, 1)
void k_all(const float* __restrict__ scores,
           const float* __restrict__ priorities,
           const int* __restrict__ countp,
           const float* __restrict__ pool,
           const float* __restrict__ summaries,
           float* __restrict__ out,
           int N, int P, int D, long long out_size) {
    extern __shared__ u32 S[];             // resolve scratch (block 0 only)
    __shared__ u32 wtot[32];
    __shared__ u32 wcnt[32];
    __shared__ u16 chunkbuf[256];
    __shared__ int wsum[32];
    __shared__ int sh_changed, sh_anyTies, sh_A;

    const int tid  = threadIdx.x;
    const int b    = blockIdx.x;
    const int gtid = b * B_THREADS + tid;
    const int lane = tid & 31, w = tid >> 5;
    const int M = N + P;

    // ==================== FRONT END ====================
    // ---- ph0: zero scratch ----
    if (gtid < NB)   g_bhist[gtid]  = 0u;
    if (gtid < RMAX) g_hist[gtid]   = 0u;
    if (gtid < PMAX) g_writer[gtid] = 0xFFFFu;
    gridbar();

    // ---- ph1: bucket histogram ----
    if (gtid < M) {
        float v = (gtid < N) ? scores[gtid] : priorities[gtid - N];
        atomicAdd(&g_bhist[bucketOf(v)], 1u);
    }
    gridbar();

    // ---- ph2a: block-local scan of this block's 128-bucket segment ----
    u32 h2 = 0, incl2 = 0;
    {
        if (tid < 128) h2 = LDCG32(&g_bhist[b * 128 + tid]);
        incl2 = blockScanIncl<128>(h2, tid, lane, w, wtot);
        if (tid == 0) g_bpart[b] = wtot[0] + wtot[1] + wtot[2] + wtot[3];
    }
    gridbar();

    // ---- ph2b: block0 exclusive-scans g_bpart in place ----
    if (b == 0) {
        u32 hB = (tid < 128) ? LDCG32(&g_bpart[tid]) : 0u;
        u32 inclB = blockScanIncl<128>(hB, tid, lane, w, wtot);
        __syncthreads();
        if (tid < 128) g_bpart[tid] = inclB - hB;
    }
    gridbar();

    // ---- ph2c: final bucket prefixes + cursors ----
    if (tid < 128) {
        u32 off = LDCG32(&g_bpart[b]);
        u32 pre = off + (incl2 - h2);
        int idx = b * 128 + tid;
        g_bprefix[idx] = pre;
        g_bcur[idx]    = pre;
    }
    gridbar();

    // ---- ph3: scatter okeys by bucket ----
    if (gtid < M) {
        float v = (gtid < N) ? scores[gtid] : priorities[gtid - N];
        u32 pos = atomicAdd(&g_bcur[bucketOf(v)], 1u);
        g_bdata[pos] = okey(v);
    }
    gridbar();

    // ---- ph4: exact ranks + classify partials ----
    if (gtid < M) {
        float v = (gtid < N) ? scores[gtid] : priorities[gtid - N];
        u16 r;
        if (!(v > 0.0f)) {
            r = 0;
        } else {
            int bb = bucketOf(v);
            u32 k = okey(v);
            u32 s0 = LDCG32(&g_bprefix[bb]), e0 = LDCG32(&g_bcur[bb]);
            u32 c = 0;
            for (u32 j = s0; j < e0; ++j) c += (LDCG32(&g_bdata[j]) < k) ? 1u : 0u;
            r = (u16)(s0 + c);
        }
        if (gtid < N) g_rank_scores[gtid] = r; else g_rank_prior[gtid - N] = r;
    }
    const bool f = (gtid < N) && (scores[gtid] > 0.5f);
    u32 fmask = __ballot_sync(0xFFFFFFFFu, f);
    const u32 lanepref = __popc(fmask & ((1u << lane) - 1u));
    if (lane == 0) wcnt[w] = __popc(fmask);
    __syncthreads();
    if (tid == 0) {
        u32 tot = 0;
        #pragma unroll
        for (int j = 0; j < 32; ++j) tot += wcnt[j];
        g_cpart[b] = tot;
    }
    gridbar();

    // ---- ph5: block0 scans g_cpart -> g_coff; metas ----
    if (b == 0) {
        u32 hC = (tid < 128) ? LDCG32(&g_cpart[tid]) : 0u;
        u32 inclC = blockScanIncl<128>(hC, tid, lane, w, wtot);
        if (tid < 128) g_coff[tid] = inclC - hC;
        if (tid == 0) {
            int total = (int)(wtot[0] + wtot[1] + wtot[2] + wtot[3]);
            int C0 = *countp;
            int room = P - C0; if (room < 0) room = 0;
            g_T    = (total > room) ? total - room : 0;
            g_fc   = C0 + ((total < room) ? total : room);
            g_room = room;
            g_C0   = C0;
        }
    }
    gridbar();

    // ---- ph6: classify writes (appends + phase-2 stream) ----
    if (f) {
        int room = LDCGI(&g_room);
        int C0   = LDCGI(&g_C0);
        u32 woff = 0;
        #pragma unroll
        for (int j = 0; j < 32; ++j) if (j < w) woff += wcnt[j];
        int r = (int)(LDCG32(&g_coff[b]) + woff + lanepref);
        if (r < room) g_writer[C0 + r] = (u16)gtid;
        else          g_si[r - room]   = (u16)gtid;
    }
    gridbar();

    // ---- ph7: pool ranks + hist, stream ranks ----
    {
        int T = LDCGI(&g_T);
        if (gtid < P) {
            u16 wv = LDCG16(&g_writer[gtid]);
            u16 pr = (wv != 0xFFFFu) ? LDCG16(&g_rank_scores[wv])
                                     : LDCG16(&g_rank_prior[gtid]);
            g_psr[gtid] = pr;
            atomicAdd(&g_hist[pr], 1u);
        }
        if (gtid < T) {
            u16 it = LDCG16(&g_si[gtid]);
            g_sr[gtid] = LDCG16(&g_rank_scores[it]);
        }
    }
    gridbar();

    // ---- ph8a: psBelow partials (160/block) + chunk sorts (blocks 0..63) ----
    u32 h8 = 0, incl8 = 0;
    {
        if (tid < 160) h8 = LDCG32(&g_hist[b * 160 + tid]);
        incl8 = blockScanIncl<160>(h8, tid, lane, w, wtot);
        if (tid == 0) g_ppart[b] = wtot[0] + wtot[1] + wtot[2] + wtot[3] + wtot[4];
        __syncthreads();
    }
    if (b < 64) {
        int T = LDCGI(&g_T);
        if (tid < 256) {
            int i = (b << 8) + tid;
            chunkbuf[tid] = (i < T) ? LDCG16(&g_sr[i]) : (u16)0xFFFFu;
        }
        __syncthreads();
        for (int k = 2; k <= 256; k <<= 1) {
            for (int j = k >> 1; j > 0; j >>= 1) {
                if (tid < 256) {
                    int p = tid ^ j;
                    if (p > tid) {
                        u16 x = chunkbuf[tid], y = chunkbuf[p];
                        bool up = ((tid & k) == 0);
                        if (up ? (x > y) : (x < y)) { chunkbuf[tid] = y; chunkbuf[p] = x; }
                    }
                }
                __syncthreads();
            }
        }
        if (tid < 256) g_chunkS[(b << 8) + tid] = chunkbuf[tid];
    }
    gridbar();

    // ---- ph8b: block0 scans g_ppart -> g_poff ----
    if (b == 0) {
        u32 hP = (tid < 128) ? LDCG32(&g_ppart[tid]) : 0u;
        u32 inclP = blockScanIncl<128>(hP, tid, lane, w, wtot);
        if (tid < 128) g_poff[tid] = inclP - hP;
    }
    gridbar();

    // ---- ph8c: psBelow -> g_cursor ----
    // NOTE: no gridbar after this phase. The count phase below reads only
    // g_sr / g_chunkS (ordered two barriers ago); g_cursor's first reader is
    // the resolve phase, which sits behind the count->resolve gridbar.
    if (tid < 160) {
        u32 off = LDCG32(&g_poff[b]);
        g_cursor[b * 160 + tid] = off + (incl8 - h8);
    }

    // ==================== COUNT (4096 warps, as R12) =======================
    // g_sr / g_chunkS are written in block-aligned contiguous ranges, so a
    // block's L1 can only hold lines it wrote itself -> plain loads are safe
    // and keep the hot binary searches L1-cached.
    {
        const int T = LDCGI(&g_T);
        const int warpsTotal = (G_BLOCKS * B_THREADS) >> 5;   // 4096
        const int gw = gtid >> 5;
        for (int q = gw; q < T; q += warpsTotal) {
            const u16 r = g_sr[q];
            const int c0 = q >> 8;
            u32 cnt = 0;
            for (int ch = lane; ch < c0; ch += 32) {
                const u16* a = g_chunkS + (ch << 8);
                int lo = 0, hi = 256;
                while (lo < hi) { int m = (lo + hi) >> 1; if (a[m] < r) lo = m + 1; else hi = m; }
                cnt += (u32)lo;
            }
            for (int j = (q & ~255) + lane; j < q; j += 32)
                cnt += (g_sr[j] < r) ? 1u : 0u;
            #pragma unroll
            for (int o = 16; o; o >>= 1) cnt += __shfl_down_sync(0xFFFFFFFFu, cnt, o);
            if (lane == 0) g_Bq[q] = cnt;
        }
    }
    gridbar();

    // ==================== RESOLVE (block 0; verified R12 @1024 threads) ====
    if (b == 0) {
        u32* gU  = S;                          // RMAX
        u32* par = S + RMAX;                   // NMAX
        u16* wr  = (u16*)(S + RMAX + NMAX);    // PMAX
        const int nthr = B_THREADS;            // 1024
        const int T = LDCGI(&g_T);

        // ---- accept: 16 items/thread (R12 layout) ----
        {
            int myCnt = 0;
            u32 amask = 0;
            const int q0 = tid * 16;
            u16 rs[16];
            #pragma unroll
            for (int j = 0; j < 16; ++j) {
                int q = q0 + j;
                if (q < T) {
                    u16 r = LDCG16(&g_sr[q]);
                    rs[j] = r;
                    int bq = (int)LDCG32(&g_Bq[q]);
                    int psb = (int)LDCG32(&g_cursor[r]);
                    if (psb + bq >= q + 1) { amask |= (1u << j); myCnt++; }
                }
            }
            int vv = myCnt;
            #pragma unroll
            for (int o = 1; o < 32; o <<= 1) {
                int t = __shfl_up_sync(0xFFFFFFFFu, vv, o);
                if (lane >= o) vv += t;
            }
            if (lane == 31) wsum[w] = vv;
            __syncthreads();
            if (w == 0) {
                int ww = wsum[lane];
                #pragma unroll
                for (int o = 1; o < 32; o <<= 1) {
                    int t = __shfl_up_sync(0xFFFFFFFFu, ww, o);
                    if (lane >= o) ww += t;
                }
                wsum[lane] = ww;
            }
            __syncthreads();
            int jbase = (vv - myCnt) + ((w > 0) ? wsum[w - 1] : 0);
            if (tid == 0) sh_A = wsum[31];
            #pragma unroll
            for (int j = 0; j < 16; ++j) {
                if (amask & (1u << j)) {
                    int q = q0 + j;
                    g_bdata[jbase++] = ((u32)rs[j] << 14) | (u32)LDCG16(&g_si[q]);
                }
            }
            __syncthreads();
        }
        const int A = sh_A;

        for (int i = tid; i < PMAX; i += nthr)
            wr[i] = (i < P) ? LDCG16(&g_writer[i]) : (u16)0xFFFFu;
        __syncthreads();

        if (A > 0) {
            const int UN = P + A;

            for (int j = tid; j < A; j += nthr) atomicAdd(&g_hist[g_bdata[j] >> 14], 1u);
            __syncthreads();
            {   // exclusive prefix over RMAX -> g_cursor (U cursors)
                const int CPT = RMAX / B_THREADS;   // 20
                const int base = tid * CPT;
                u32 s = 0;
                #pragma unroll
                for (int j = 0; j < CPT; ++j) s += LDCG32(&g_hist[base + j]);
                u32 vv = s;
                #pragma unroll
                for (int o = 1; o < 32; o <<= 1) {
                    u32 t = __shfl_up_sync(0xFFFFFFFFu, vv, o);
                    if (lane >= o) vv += t;
                }
                if (lane == 31) wsum[w] = (int)vv;
                __syncthreads();
                if (w == 0) {
                    u32 ww = (u32)wsum[lane];
                    #pragma unroll
                    for (int o = 1; o < 32; o <<= 1) {
                        u32 t = __shfl_up_sync(0xFFFFFFFFu, ww, o);
                        if (lane >= o) ww += t;
                    }
                    wsum[lane] = (int)ww;
                }
                __syncthreads();
                u32 run = (vv - s) + ((w > 0) ? (u32)wsum[w - 1] : 0u);
                #pragma unroll
                for (int j = 0; j < CPT; ++j) {
                    u32 h = LDCG32(&g_hist[base + j]);
                    g_cursor[base + j] = run;
                    run += h;
                }
                __syncthreads();
            }
            // scatter: elem = rank<<17 | type<<16 | id
            for (int i = tid; i < P; i += nthr) {
                u32 r = (u32)LDCG16(&g_psr[i]);
                u32 pos = atomicAdd(&g_cursor[r], 1u);
                gU[pos] = (r << 17) | (u32)i;
            }
            for (int j = tid; j < A; j += nthr) {
                u32 r = g_bdata[j] >> 14;
                u32 pos = atomicAdd(&g_cursor[r], 1u);
                gU[pos] = (r << 17) | 0x10000u | (u32)j;
            }
            __syncthreads();

            if (tid == 0) sh_anyTies = 0;
            __syncthreads();
            for (int p = tid; p + 1 < UN; p += nthr)
                if ((gU[p] >> 17) == (gU[p + 1] >> 17)) sh_anyTies = 1;
            __syncthreads();

            const int MAXIT = 32;
            for (int it = 0; it < MAXIT; ++it) {
                for (int j = tid; j < A; j += nthr) {
                    u32 e = gU[j];
                    par[j] = (e & 0x10000u) ? (e & 0xFFFFu) : (0x80000000u | (e & 0xFFFFu));
                }
                __syncthreads();
                for (int rd = 0; rd < 15; ++rd) {
                    if (tid == 0) sh_changed = 0;
                    __syncthreads();
                    for (int j = tid; j < A; j += nthr) {
                        u32 pv = par[j];
                        if (!(pv & 0x80000000u)) {
                            u32 g = par[pv];
                            par[j] = g;
                            if (!(g & 0x80000000u)) sh_changed = 1;
                        }
                    }
                    __syncthreads();
                    if (!sh_changed) break;
                }
                if (!sh_anyTies) break;
                if (it == MAXIT - 1) break;
                if (tid == 0) sh_changed = 0;
                __syncthreads();
                for (int p = tid; p < UN; p += nthr) {
                    u32 r = gU[p] >> 17;
                    bool leader = (p == 0) || ((gU[p - 1] >> 17) != r);
                    if (leader && p + 1 < UN && (gU[p + 1] >> 17) == r) {
                        int len = 1;
                        while (p + len < UN && (gU[p + len] >> 17) == r) len++;
                        bool ch = false;
                        for (int a = 1; a < len; ++a) {
                            u32 x = gU[p + a];
                            u32 sx = (x & 0x10000u) ? (par[x & 0xFFFFu] & 0xFFFFu) : (x & 0xFFFFu);
                            u32 kx = (sx << 1) | ((x >> 16) & 1u);
                            int bb = a;
                            while (bb > 0) {
                                u32 y = gU[p + bb - 1];
                                u32 sy = (y & 0x10000u) ? (par[y & 0xFFFFu] & 0xFFFFu) : (y & 0xFFFFu);
                                u32 ky = (sy << 1) | ((y >> 16) & 1u);
                                if (ky <= kx) break;
                                gU[p + bb] = y; bb--; ch = true;
                            }
                            gU[p + bb] = x;
                        }
                        if (ch) sh_changed = 1;
                    }
                }
                __syncthreads();
                if (!sh_changed) break;
            }

            for (int pos = A + tid; pos < UN; pos += nthr) {
                u32 e = gU[pos];
                if (e & 0x10000u) {
                    u32 j = e & 0xFFFFu;
                    u32 s = par[j] & 0xFFFFu;
                    if (s < (u32)P) wr[s] = (u16)(g_bdata[j] & 0x3FFFu);
                }
            }
            __syncthreads();
        }

        // epilogue: final writer map + priorities + count
        const long long obase = (long long)P * (long long)D;
        for (int i = tid; i < P; i += nthr) {
            u16 wv = wr[i];
            g_writer[i] = wv;
            if (obase + i < out_size)
                out[obase + i] = (wv != 0xFFFFu) ? scores[wv] : priorities[i];
        }
        if (tid == 0 && obase + P < out_size)
            out[obase + P] = (float)LDCGI(&g_fc);
    }
    gridbar();

    // ==================== COPY (4096 warps grid-strided, float4) ===========
    // g_writer was rewritten by block 0 post-barrier -> .cg loads.
    if ((D & 3) == 0) {
        const int D4 = D >> 2;
        const long long total = (long long)P * (long long)D4;
        const long long stride = (long long)G_BLOCKS * B_THREADS;
        for (long long idx = gtid; idx < total; idx += stride) {
            int row = (int)(idx / D4);
            int col = (int)(idx - (long long)row * D4);
            u16 wv = LDCG16(&g_writer[row]);
            const float4* src = (wv == 0xFFFFu)
                ? (const float4*)(pool + (long long)row * D)
                : (const float4*)(summaries + (long long)wv * D);
            ((float4*)(out + (long long)row * D))[col] = src[col];
        }
    } else {
        const long long total = (long long)P * (long long)D;
        const long long stride = (long long)G_BLOCKS * B_THREADS;
        for (long long idx = gtid; idx < total; idx += stride) {
            int row = (int)(idx / D);
            int col = (int)(idx - (long long)row * D);
            u16 wv = LDCG16(&g_writer[row]);
            const float* src = (wv == 0xFFFFu) ? (pool + (long long)row * D)
                                               : (summaries + (long long)wv * D);
            out[(long long)row * D + col] = src[col];
        }
    }
}

// ---------------------------------------------------------------------------
// Inputs (metadata order): summaries[N,D] f32, scores[N] f32, pool[P,D] f32,
// priorities[P] f32, count i32 scalar.
// Output: concat(pool_out[P*D], priorities[P], count) as f32.
// ---------------------------------------------------------------------------
extern "C" void kernel_launch(void* const* d_in, const int* in_sizes, int n_in,
                              void* d_out, int out_size) {
    const float* summaries  = (const float*)d_in[0];
    const float* scores     = (const float*)d_in[1];
    const float* pool       = (const float*)d_in[2];
    const float* priorities = (const float*)d_in[3];
    const int*   countp     = (const int*)d_in[4];

    const int N = in_sizes[1];
    const int P = in_sizes[3];
    const int D = (N > 0) ? (in_sizes[0] / N) : 0;
    float* out = (float*)d_out;

    const int smem = (RMAX + NMAX) * 4 + PMAX * 2;   // 155,648 (resolve scratch)
    cudaFuncSetAttribute(k_all, cudaFuncAttributeMaxDynamicSharedMemorySize, smem);

    k_all<<<G_BLOCKS, B_THREADS, smem>>>(scores, priorities, countp,
                                         pool, summaries, out,
                                         N, P, D, (long long)out_size);
}